// round 2
// baseline (speedup 1.0000x reference)
#include <cuda_runtime.h>
#include <cuda_bf16.h>
#include <math.h>

#define BMAX 2048
#define KD   256
#define PD   256
#define SD   10
#define NMAX 512   // KD + PD

// per-batch partial results (allocation-free scratch)
__device__ float g_pen[BMAX];
__device__ float g_lmse[BMAX];

__global__ __launch_bounds__(256)
void vil_main_kernel(const float* __restrict__ y_pred,
                     const float* __restrict__ y_true,
                     const float* __restrict__ Pp,
                     const float* __restrict__ params,
                     const float* __restrict__ Xs)
{
    const int b   = blockIdx.x;
    const int tid = threadIdx.x;
    const int lane = tid & 31;
    const int w    = tid >> 5;

    __shared__ float xs[SD][KD];       // masked X, 10 KB
    __shared__ float mags[SD][NMAX];   // |C| or -1, 20 KB
    __shared__ float hms[SD];

    const int n  = (int)params[b * 3 + 0];
    const int kb = (int)params[b * 3 + 1];
    const int mb = (int)params[b * 3 + 2];
    const int nk = n - kb;

    // ---- load X[b] masked by xmask into smem ----
    const float* Xb = Xs + (size_t)b * SD * KD;
    for (int idx = tid; idx < SD * KD; idx += 256) {
        int kk = idx & (KD - 1);
        float v = Xb[idx];
        ((float*)xs)[idx] = (kk < kb) ? v : 0.0f;
    }
    __syncthreads();

    // ---- GEMM: C_p[s, j=tid] = sum_k xs[s][k] * P[b,k,j] ----
    float acc[SD];
#pragma unroll
    for (int s = 0; s < SD; s++) acc[s] = 0.0f;

    const float* Pb = Pp + (size_t)b * KD * PD + tid;
#pragma unroll 4
    for (int k4 = 0; k4 < KD; k4 += 4) {
        float p0 = Pb[(k4 + 0) * PD];
        float p1 = Pb[(k4 + 1) * PD];
        float p2 = Pb[(k4 + 2) * PD];
        float p3 = Pb[(k4 + 3) * PD];
#pragma unroll
        for (int s = 0; s < SD; s++) {
            float4 xv = *(const float4*)&xs[s][k4];   // broadcast LDS.128, conflict-free
            acc[s] = fmaf(xv.x, p0,
                     fmaf(xv.y, p1,
                     fmaf(xv.z, p2,
                     fmaf(xv.w, p3, acc[s]))));
        }
    }

    // ---- magnitudes with validity mask (-1 ranks invalid last) ----
#pragma unroll
    for (int s = 0; s < SD; s++) {
        mags[s][tid]      = (tid < kb) ? fabsf(xs[s][tid]) : -1.0f;
        mags[s][KD + tid] = (tid < nk) ? fabsf(acc[s])     : -1.0f;
    }
    __syncthreads();

    // ---- per-sample top-(m+1) via iterative max extraction (1 warp / sample) ----
    for (int s = w; s < SD; s += 8) {
        float v[16];
#pragma unroll
        for (int i = 0; i < 16; i++) v[i] = mags[s][lane + 32 * i];  // bank = lane, conflict-free

        float cmax = 0.0f, cm = 0.0f;
        for (int pass = 0;; pass++) {
            float lm = v[0];
#pragma unroll
            for (int i = 1; i < 16; i++) lm = fmaxf(lm, v[i]);
            float wm = lm;
#pragma unroll
            for (int off = 16; off; off >>= 1)
                wm = fmaxf(wm, __shfl_xor_sync(0xffffffffu, wm, off));
            if (pass == 0)  cmax = wm;
            if (pass == mb) { cm = wm; break; }
            // remove exactly ONE instance of wm (matches sort semantics on ties)
            unsigned bal = __ballot_sync(0xffffffffu, lm == wm);
            int src = __ffs(bal) - 1;
            if (lane == src) {
                bool done = false;
#pragma unroll
                for (int i = 0; i < 16; i++) {
                    if (!done && v[i] == wm) { v[i] = -3.0e38f; done = true; }
                }
            }
        }
        if (lane == 0) hms[s] = cmax / (cm + 1e-9f);
    }
    __syncthreads();

    if (tid == 0) {
        float mh = hms[0];
#pragma unroll
        for (int s = 1; s < SD; s++) mh = fmaxf(mh, hms[s]);
        float yp = y_pred[b];
        float pen = ((mb + 1) <= n) ? fmaxf(mh - yp, 0.0f) : 0.0f;
        g_pen[b] = pen;
        float lp = log2f(fmaxf(yp, 1e-9f));
        float lt = log2f(fmaxf(y_true[b], 1e-9f));
        float d  = lt - lp;
        g_lmse[b] = d * d;
    }
}

__global__ __launch_bounds__(256)
void vil_finalize_kernel(float* __restrict__ out, int out_size, int Bn)
{
    __shared__ float sp[256], sl[256];
    int t = threadIdx.x;
    float p = 0.0f, l = 0.0f;
    for (int i = t; i < Bn; i += 256) { p += g_pen[i]; l += g_lmse[i]; }
    sp[t] = p; sl[t] = l;
    __syncthreads();
    for (int o = 128; o; o >>= 1) {
        if (t < o) { sp[t] += sp[t + o]; sl[t] += sl[t + o]; }
        __syncthreads();
    }
    if (t == 0) {
        float lmse = sl[0] / (float)Bn;
        float viol = sp[0] / (float)Bn;
        float tot  = lmse + 0.5f * viol;
        if (out_size > 0) out[0] = tot;
        if (out_size > 1) out[1] = lmse;
        if (out_size > 2) out[2] = viol;
    }
}

extern "C" void kernel_launch(void* const* d_in, const int* in_sizes, int n_in,
                              void* d_out, int out_size)
{
    const float* y_pred = (const float*)d_in[0];
    const float* y_true = (const float*)d_in[1];
    const float* Pp     = (const float*)d_in[2];
    const float* params = (const float*)d_in[3];
    const float* Xs     = (const float*)d_in[4];
    float* out = (float*)d_out;

    int Bn = in_sizes[0];
    if (Bn > BMAX) Bn = BMAX;

    vil_main_kernel<<<Bn, 256>>>(y_pred, y_true, Pp, params, Xs);
    vil_finalize_kernel<<<1, 256>>>(out, out_size, Bn);
}

// round 3
// speedup vs baseline: 1.4138x; 1.4138x over previous
#include <cuda_runtime.h>
#include <cuda_bf16.h>
#include <math.h>

#define BMAX 2048
#define KD   256
#define PD   256
#define SD   10
#define SP   5     // sample pairs

// per-batch partial results (allocation-free scratch)
__device__ float g_pen[BMAX];
__device__ float g_lmse[BMAX];

typedef unsigned long long u64;

__device__ __forceinline__ u64 ffma2(u64 a, u64 b, u64 c) {
    u64 d;
    asm("fma.rn.f32x2 %0, %1, %2, %3;" : "=l"(d) : "l"(a), "l"(b), "l"(c));
    return d;
}
__device__ __forceinline__ u64 bcast2(float p) {
    u64 d; unsigned u = __float_as_uint(p);
    asm("mov.b64 %0, {%1, %1};" : "=l"(d) : "r"(u));
    return d;
}

__global__ __launch_bounds__(256)
void vil_main_kernel(const float* __restrict__ y_pred,
                     const float* __restrict__ y_true,
                     const float* __restrict__ Pp,
                     const float* __restrict__ params,
                     const float* __restrict__ Xs)
{
    const int b    = blockIdx.x;
    const int tid  = threadIdx.x;
    const int lane = tid & 31;
    const int w    = tid >> 5;

    __shared__ float2 xsp[SP][KD];    // masked X, sample-pair packed, 10 KB
    __shared__ float  cacc[SD][PD];   // X@P results, 10 KB
    __shared__ float  hms[SD];

    const int n  = (int)params[b * 3 + 0];
    const int kb = (int)params[b * 3 + 1];
    const int mb = (int)params[b * 3 + 2];
    const int nk = n - kb;

    // ---- load X[b], masked, packed as (x[2sp][k], x[2sp+1][k]) ----
    const float* Xb = Xs + (size_t)b * SD * KD;
    for (int idx = tid; idx < SP * KD; idx += 256) {
        int sp = idx >> 8;        // / KD
        int k  = idx & (KD - 1);
        float a = Xb[(2 * sp)     * KD + k];
        float c = Xb[(2 * sp + 1) * KD + k];
        if (k >= kb) { a = 0.0f; c = 0.0f; }
        xsp[sp][k] = make_float2(a, c);
    }
    __syncthreads();

    // ---- GEMM: C[s, j=tid] = sum_k x[s][k] * P[b,k,j], f32x2 over sample pairs ----
    u64 acc[SP];
#pragma unroll
    for (int sp = 0; sp < SP; sp++) acc[sp] = 0ull;

    const float* Pb = Pp + (size_t)b * KD * PD + tid;

    float pc[8], pn[8];
#pragma unroll
    for (int i = 0; i < 8; i++) pc[i] = __ldcs(Pb + i * PD);

    for (int k8 = 0; k8 < KD; k8 += 8) {
        if (k8 + 8 < KD) {
#pragma unroll
            for (int i = 0; i < 8; i++) pn[i] = __ldcs(Pb + (k8 + 8 + i) * PD);
        }
#pragma unroll
        for (int i = 0; i < 8; i += 2) {
            u64 pp0 = bcast2(pc[i]);
            u64 pp1 = bcast2(pc[i + 1]);
#pragma unroll
            for (int sp = 0; sp < SP; sp++) {
                // one LDS.128: x pairs for k8+i and k8+i+1 (broadcast, conflict-free)
                const u64* xq = (const u64*)&xsp[sp][k8 + i];
                u64 x0 = xq[0];
                u64 x1 = xq[1];
                acc[sp] = ffma2(x0, pp0, acc[sp]);
                acc[sp] = ffma2(x1, pp1, acc[sp]);
            }
        }
#pragma unroll
        for (int i = 0; i < 8; i++) pc[i] = pn[i];
    }

    // ---- unpack results to smem ----
#pragma unroll
    for (int sp = 0; sp < SP; sp++) {
        float2 v = *(float2*)&acc[sp];
        cacc[2 * sp][tid]     = v.x;
        cacc[2 * sp + 1][tid] = v.y;
    }
    __syncthreads();

    // ---- per-sample top-(m+1) via iterative max extraction (1 warp / sample) ----
    for (int s = w; s < SD; s += 8) {
        float v[16];
#pragma unroll
        for (int i = 0; i < 8; i++) {
            int idx = lane + 32 * i;
            float2 xv = xsp[s >> 1][idx];
            float x = (s & 1) ? xv.y : xv.x;
            v[i] = (idx < kb) ? fabsf(x) : -1.0f;
        }
#pragma unroll
        for (int i = 0; i < 8; i++) {
            int j = lane + 32 * i;
            v[8 + i] = (j < nk) ? fabsf(cacc[s][j]) : -1.0f;
        }

        float cmax = 0.0f, cm = 0.0f;
        for (int pass = 0;; pass++) {
            float lm = v[0];
#pragma unroll
            for (int i = 1; i < 16; i++) lm = fmaxf(lm, v[i]);
            float wm = lm;
#pragma unroll
            for (int off = 16; off; off >>= 1)
                wm = fmaxf(wm, __shfl_xor_sync(0xffffffffu, wm, off));
            if (pass == 0)  cmax = wm;
            if (pass == mb) { cm = wm; break; }
            // remove exactly ONE instance of wm (matches sort semantics on ties)
            unsigned bal = __ballot_sync(0xffffffffu, lm == wm);
            int src = __ffs(bal) - 1;
            if (lane == src) {
                bool done = false;
#pragma unroll
                for (int i = 0; i < 16; i++) {
                    if (!done && v[i] == wm) { v[i] = -3.0e38f; done = true; }
                }
            }
        }
        if (lane == 0) hms[s] = cmax / (cm + 1e-9f);
    }
    __syncthreads();

    if (tid == 0) {
        float mh = hms[0];
#pragma unroll
        for (int s = 1; s < SD; s++) mh = fmaxf(mh, hms[s]);
        float yp = y_pred[b];
        float pen = ((mb + 1) <= n) ? fmaxf(mh - yp, 0.0f) : 0.0f;
        g_pen[b] = pen;
        float lp = log2f(fmaxf(yp, 1e-9f));
        float lt = log2f(fmaxf(y_true[b], 1e-9f));
        float d  = lt - lp;
        g_lmse[b] = d * d;
    }
}

__global__ __launch_bounds__(256)
void vil_finalize_kernel(float* __restrict__ out, int out_size, int Bn)
{
    __shared__ float sp[256], sl[256];
    int t = threadIdx.x;
    float p = 0.0f, l = 0.0f;
    for (int i = t; i < Bn; i += 256) { p += g_pen[i]; l += g_lmse[i]; }
    sp[t] = p; sl[t] = l;
    __syncthreads();
    for (int o = 128; o; o >>= 1) {
        if (t < o) { sp[t] += sp[t + o]; sl[t] += sl[t + o]; }
        __syncthreads();
    }
    if (t == 0) {
        float lmse = sl[0] / (float)Bn;
        float viol = sp[0] / (float)Bn;
        float tot  = lmse + 0.5f * viol;
        if (out_size > 0) out[0] = tot;
        if (out_size > 1) out[1] = lmse;
        if (out_size > 2) out[2] = viol;
    }
}

extern "C" void kernel_launch(void* const* d_in, const int* in_sizes, int n_in,
                              void* d_out, int out_size)
{
    const float* y_pred = (const float*)d_in[0];
    const float* y_true = (const float*)d_in[1];
    const float* Pp     = (const float*)d_in[2];
    const float* params = (const float*)d_in[3];
    const float* Xs     = (const float*)d_in[4];
    float* out = (float*)d_out;

    int Bn = in_sizes[0];
    if (Bn > BMAX) Bn = BMAX;

    vil_main_kernel<<<Bn, 256>>>(y_pred, y_true, Pp, params, Xs);
    vil_finalize_kernel<<<1, 256>>>(out, out_size, Bn);
}